// round 12
// baseline (speedup 1.0000x reference)
#include <cuda_runtime.h>

#define B_ 128
#define T_ 1024
#define N_ 64

// Per-batch losses + completion counter; reduced by the last-arriving block.
__device__ float g_loss[B_];
__device__ unsigned g_count = 0;   // wraps to 0 every launch via atomicInc(.,B_-1)

typedef unsigned long long u64;

__device__ __forceinline__ u64 pack2(float lo, float hi) {
    u64 d;
    asm("mov.b64 %0, {%1, %2};" : "=l"(d)
        : "r"(__float_as_uint(lo)), "r"(__float_as_uint(hi)));
    return d;
}
__device__ __forceinline__ float unpack_sum(u64 v) {
    unsigned a, b;
    asm("mov.b64 {%0, %1}, %2;" : "=r"(a), "=r"(b) : "l"(v));
    return __uint_as_float(a) + __uint_as_float(b);
}
__device__ __forceinline__ u64 ffma2(u64 a, u64 b, u64 c) {
    u64 d;
    asm("fma.rn.f32x2 %0, %1, %2, %3;" : "=l"(d) : "l"(a), "l"(b), "l"(c));
    return d;
}
__device__ __forceinline__ u64 fadd2(u64 a, u64 b) {
    u64 d;
    asm("add.rn.f32x2 %0, %1, %2;" : "=l"(d) : "l"(a), "l"(b));
    return d;
}

// Half-dot (32 MACs): 8x LDS.128 + 16x FFMA2 into 4 accs, reduced to one u64.
__device__ __forceinline__ u64 halfdot(const ulonglong2* __restrict__ a4,
                                       int base8,
                                       const u64* __restrict__ Eh) {
    u64 acc0 = 0ull, acc1 = 0ull, acc2 = 0ull, acc3 = 0ull;
#pragma unroll
    for (int k = 0; k < 8; ++k) {
        ulonglong2 v = a4[base8 + k];
        if (k & 1) {
            acc2 = ffma2(v.x, Eh[2 * k],     acc2);
            acc3 = ffma2(v.y, Eh[2 * k + 1], acc3);
        } else {
            acc0 = ffma2(v.x, Eh[2 * k],     acc0);
            acc1 = ffma2(v.y, Eh[2 * k + 1], acc1);
        }
    }
    acc0 = fadd2(acc0, acc1);
    acc2 = fadd2(acc2, acc3);
    return fadd2(acc0, acc2);
}

// Main-loop step with MID-STEP barrier: own-warp half of the dot runs BEFORE
// the bar (overlapping barrier wait / warp skew); only the other warp's half
// (and the renorm broadcast) sit after it. Double-buffering makes the pre-bar
// reads race-free (old parity only).
#define STEP(SRC, DST, RENORM)                                             \
    {                                                                      \
        float p_pref = Pb[max(pidx, 0) * N_ + j];                          \
        pidx += pinc;                                                      \
        float mult = __expf(p_cur);                                        \
        const ulonglong2* a4 = (const ulonglong2*)(SRC);                   \
        u64 own = halfdot(a4, own8, Ec);                                   \
        asm volatile("bar.sync %0, 64;" :: "r"(barid) : "memory");         \
        if (RENORM) {                                                      \
            float a0 = (SRC)[0];                                           \
            mult *= __fdividef(1.0f, a0);                                  \
            cacc += __logf(a0);                                            \
        }                                                                  \
        u64 oth = halfdot(a4, oth8, Ec + 16);                              \
        float s = unpack_sum(fadd2(own, oth));                             \
        my_v = s * mult;                                                   \
        (DST)[j] = my_v;                                                   \
        __syncwarp();                                                      \
        p_cur = p_nxt;                                                     \
        p_nxt = p_pref;                                                    \
    }

// 128 threads: warps 0-1 FORWARD half-chain, warps 2-3 BACKWARD half-chain,
// meeting at m = ceil(L/2): Z = sum_j alpha_m[j] * w_m[j]. Last-arriving
// block reduces g_loss into out.
__global__ void __launch_bounds__(2 * N_, 1) crf_forward_kernel(
    const float* __restrict__ pot,     // (B,T,N)
    const int*   __restrict__ tags,    // (B,T)
    const int*   __restrict__ seqlen,  // (B,)
    const float* __restrict__ ck,      // (N,N)
    const float* __restrict__ sw,      // (B,)
    float*       __restrict__ out)     // (1,)
{
    const int tid = threadIdx.x;
    const int b   = blockIdx.x;
    const int grp = tid >> 6;          // 0 = forward, 1 = backward
    const int w   = (tid >> 5) & 1;    // warp index within group
    const int j   = tid & (N_ - 1);
    const int len = seqlen[b];
    const int L   = len - 1;           // len >= T/2 = 512
    const int barid = 1 + grp;
    const int own8 = 8 * w;            // ulonglong2 index of own half
    const int oth8 = 8 * (1 - w);

    __shared__ __align__(16) float buf[2][2][N_];  // [grp][parity][state]
    __shared__ float red2[2 * N_];
    __shared__ float c_share;
    __shared__ int   is_last;

    // E registers, ordered [own half 16][other half 16].
    // forward (grp 0): element(r) = exp(ck[r*N + j]); backward: exp(ck[j*N + r]).
    u64 Ec[32];
    {
        const int strd = (grp == 0) ? N_ : 1;
        const int offs = (grp == 0) ? j : j * N_;
#pragma unroll
        for (int half = 0; half < 2; ++half) {
            const int base = 32 * ((half == 0) ? w : (1 - w));
#pragma unroll
            for (int k = 0; k < 8; ++k) {
                Ec[16 * half + 2 * k] =
                    pack2(__expf(ck[(base + 4 * k)     * strd + offs]),
                          __expf(ck[(base + 4 * k + 1) * strd + offs]));
                Ec[16 * half + 2 * k + 1] =
                    pack2(__expf(ck[(base + 4 * k + 2) * strd + offs]),
                          __expf(ck[(base + 4 * k + 3) * strd + offs]));
            }
        }
    }

    const float* Pb   = pot  + (size_t)b * T_ * N_;
    const int*   tagb = tags + b * T_;

    // ---------------- sequence score ----------------
    float ss = 0.f;
    for (int t = tid; t < len; t += 2 * N_) {
        int tg = tagb[t];
        ss += Pb[t * N_ + tg];
        if (t >= 1) ss += ck[tagb[t - 1] * N_ + tg];
    }
    red2[tid] = ss;
    __syncthreads();
#pragma unroll
    for (int off = N_; off >= 1; off >>= 1) {
        if (tid < off) red2[tid] += red2[tid + off];
        __syncthreads();
    }
    const float seq_score = red2[0];
    __syncthreads();

    const int stepsF = (L + 1) >> 1;   // forward applies t = 1..stepsF
    const int stepsB = L - stepsF;     // backward applies t = L..stepsF+1
    const int niter  = stepsF;

    // ---------------- init ----------------
    float cacc, my_v, p_cur, p_nxt;
    int pidx, pinc;
    if (grp == 0) {
        cacc  = Pb[0];
        my_v  = __expf(Pb[j] - cacc);
        p_cur = Pb[1 * N_ + j];
        p_nxt = Pb[2 * N_ + j];
        pidx  = 3;   pinc = 1;
    } else {
        cacc  = Pb[L * N_];
        my_v  = __expf(Pb[L * N_ + j] - cacc);
        p_cur = Pb[(L - 1) * N_ + j];
        p_nxt = Pb[(L - 2) * N_ + j];
        pidx  = L - 3;   pinc = -1;
    }
    float* b0 = &buf[grp][0][0];
    float* b1 = &buf[grp][1][0];
    b0[j] = my_v;
    __syncwarp();   // own half visible; the first STEP's mid-bar covers the rest

    // ---------------- main loop: uniform, unrolled x4, renorm every 4 ------
    const int nmain = (niter >= 3) ? ((niter - 2) & ~3) : 0;
    for (int i = 0; i < nmain; i += 4) {
        STEP(b0, b1, true)
        STEP(b1, b0, false)
        STEP(b0, b1, false)
        STEP(b1, b0, false)
    }

    // ---------------- tail (2..5 iters, predicated, bar-first) -------------
    int cur = 0;
    for (int i = nmain; i < niter; ++i) {
        float* src = cur ? b1 : b0;
        float* dst = cur ? b0 : b1;
        const bool active      = (grp == 0) || (i < stepsB);
        const bool last_active = (grp == 1) && (i == stepsB - 1);
        asm volatile("bar.sync %0, 64;" :: "r"(barid) : "memory");
        float p_pref = Pb[max(pidx, 0) * N_ + j];
        pidx += pinc;
        float mult = last_active ? 1.0f : __expf(p_cur);
        if (((i & 3) == 0) && active) {
            float a0 = src[0];
            mult *= __fdividef(1.0f, a0);
            cacc += __logf(a0);
        }
        const ulonglong2* a4 = (const ulonglong2*)src;
        u64 own = halfdot(a4, own8, Ec);
        u64 oth = halfdot(a4, oth8, Ec + 16);
        float s = unpack_sum(fadd2(own, oth));
        if (active) my_v = s * mult;
        dst[j] = my_v;
        __syncwarp();
        p_cur = p_nxt;
        p_nxt = p_pref;
        cur ^= 1;
    }

    // ---------------- combine: Z = sum_j alpha_m[j] * w_m[j] ----------------
    if (tid == N_) c_share = cacc;            // backward group's log-offset
    __syncthreads();
    if (grp == 0) red2[j] = buf[0][cur][j] * buf[1][cur][j];
    __syncthreads();
#pragma unroll
    for (int off = N_ / 2; off >= 1; off >>= 1) {
        if (tid < off) red2[tid] += red2[tid + off];
        __syncthreads();
    }

    if (tid == 0) {
        float log_norm = cacc + c_share + logf(red2[0]);
        g_loss[b] = -(seq_score - log_norm) * sw[b];
        __threadfence();
        unsigned old = atomicInc(&g_count, B_ - 1);   // wraps -> self-resetting
        is_last = (old == B_ - 1);
    }
    __syncthreads();

    // ---------------- last block reduces all losses ----------------
    if (is_last) {
        volatile float* gl = g_loss;      // bypass L1 (other SMs' writes)
        red2[tid] = gl[tid];              // 128 threads == B_ entries
        __syncthreads();
#pragma unroll
        for (int off = N_; off >= 1; off >>= 1) {
            if (tid < off) red2[tid] += red2[tid + off];
            __syncthreads();
        }
        if (tid == 0) out[0] = red2[0] * (1.0f / (float)B_);
    }
}

extern "C" void kernel_launch(void* const* d_in, const int* in_sizes, int n_in,
                              void* d_out, int out_size)
{
    const float* pot    = (const float*)d_in[0];
    const int*   tags   = (const int*)  d_in[1];
    const int*   seqlen = (const int*)  d_in[2];
    const float* ck     = (const float*)d_in[3];
    const float* sw     = (const float*)d_in[4];

    crf_forward_kernel<<<B_, 2 * N_>>>(pot, tags, seqlen, ck, sw, (float*)d_out);
}

// round 14
// speedup vs baseline: 1.0535x; 1.0535x over previous
#include <cuda_runtime.h>

#define B_ 128
#define T_ 1024
#define N_ 64

// Per-batch losses + completion counter; reduced by the last-arriving block.
__device__ float g_loss[B_];
__device__ unsigned g_count = 0;   // wraps to 0 every launch via atomicInc(.,B_-1)

typedef unsigned long long u64;

__device__ __forceinline__ u64 pack2(float lo, float hi) {
    u64 d;
    asm("mov.b64 %0, {%1, %2};" : "=l"(d)
        : "r"(__float_as_uint(lo)), "r"(__float_as_uint(hi)));
    return d;
}
__device__ __forceinline__ float unpack_sum(u64 v) {
    unsigned a, b;
    asm("mov.b64 {%0, %1}, %2;" : "=r"(a), "=r"(b) : "l"(v));
    return __uint_as_float(a) + __uint_as_float(b);
}
__device__ __forceinline__ u64 ffma2(u64 a, u64 b, u64 c) {
    u64 d;
    asm("fma.rn.f32x2 %0, %1, %2, %3;" : "=l"(d) : "l"(a), "l"(b), "l"(c));
    return d;
}
__device__ __forceinline__ u64 fadd2(u64 a, u64 b) {
    u64 d;
    asm("add.rn.f32x2 %0, %1, %2;" : "=l"(d) : "l"(a), "l"(b));
    return d;
}

// Dual dot products (states A and B) sharing one pass of 16x LDS.128 over the
// alpha vector: 64x FFMA2 total, 4 accumulators per state.
#define DUALDOT(SRC, SA, SB)                                               \
    {                                                                      \
        const ulonglong2* a4_ = (const ulonglong2*)(SRC);                  \
        u64 A0 = 0ull, A1 = 0ull, A2 = 0ull, A3 = 0ull;                    \
        u64 B0 = 0ull, B1 = 0ull, B2 = 0ull, B3 = 0ull;                    \
        _Pragma("unroll")                                                  \
        for (int k = 0; k < 16; ++k) {                                     \
            ulonglong2 v = a4_[k];                                         \
            if (k & 1) {                                                   \
                A2 = ffma2(v.x, EcA[2 * k],     A2);                       \
                A3 = ffma2(v.y, EcA[2 * k + 1], A3);                       \
                B2 = ffma2(v.x, EcB[2 * k],     B2);                       \
                B3 = ffma2(v.y, EcB[2 * k + 1], B3);                       \
            } else {                                                       \
                A0 = ffma2(v.x, EcA[2 * k],     A0);                       \
                A1 = ffma2(v.y, EcA[2 * k + 1], A1);                       \
                B0 = ffma2(v.x, EcB[2 * k],     B0);                       \
                B1 = ffma2(v.y, EcB[2 * k + 1], B1);                       \
            }                                                              \
        }                                                                  \
        A0 = fadd2(A0, A1); A2 = fadd2(A2, A3); A0 = fadd2(A0, A2);        \
        B0 = fadd2(B0, B1); B2 = fadd2(B2, B3); B0 = fadd2(B0, B2);        \
        (SA) = unpack_sum(A0);                                             \
        (SB) = unpack_sum(B0);                                             \
    }

// One scan step, intra-warp only: STS -> __syncwarp -> LDS. No block barrier.
#define STEP(SRC, DST, RENORM)                                             \
    {                                                                      \
        const float* prow = Pb + max(pidx, 0) * N_;                        \
        float p_pref0 = prow[j0];                                          \
        float p_pref1 = prow[j1];                                          \
        pidx += pinc;                                                      \
        float mult0 = __expf(p_cur0);                                      \
        float mult1 = __expf(p_cur1);                                      \
        if (RENORM) {                                                      \
            float a0 = (SRC)[0];                                           \
            float r  = __fdividef(1.0f, a0);                               \
            mult0 *= r;  mult1 *= r;                                       \
            cacc += __logf(a0);                                            \
        }                                                                  \
        float sA, sB;                                                      \
        DUALDOT(SRC, sA, sB)                                               \
        my0 = sA * mult0;                                                  \
        my1 = sB * mult1;                                                  \
        (DST)[j0] = my0;                                                   \
        (DST)[j1] = my1;                                                   \
        __syncwarp();                                                      \
        p_cur0 = p_nxt0;  p_nxt0 = p_pref0;                                \
        p_cur1 = p_nxt1;  p_nxt1 = p_pref1;                                \
    }

// 64 threads (2 warps): warp 0 = FORWARD half-chain, warp 1 = BACKWARD
// half-chain; each lane owns states {lane, lane+32}. All step-to-step
// synchronization is __syncwarp (no block barrier, no cross-warp skew).
// Meet at m = ceil(L/2): Z = sum_j alpha_m[j] * w_m[j]. Last-arriving block
// reduces g_loss into out.
__global__ void __launch_bounds__(N_, 1) crf_forward_kernel(
    const float* __restrict__ pot,     // (B,T,N)
    const int*   __restrict__ tags,    // (B,T)
    const int*   __restrict__ seqlen,  // (B,)
    const float* __restrict__ ck,      // (N,N)
    const float* __restrict__ sw,      // (B,)
    float*       __restrict__ out)     // (1,)
{
    const int tid  = threadIdx.x;
    const int b    = blockIdx.x;
    const int grp  = tid >> 5;         // 0 = forward, 1 = backward
    const int lane = tid & 31;
    const int j0   = lane;             // first owned state
    const int j1   = lane + 32;        // second owned state
    const int len  = seqlen[b];
    const int L    = len - 1;          // len >= T/2 = 512

    __shared__ __align__(16) float buf[2][2][N_];  // [grp][parity][state]
    __shared__ float red2[2 * N_];
    __shared__ float c_share;
    __shared__ int   is_last;

    // E registers: two columns (fwd) / rows (bwd) of exp(ck), 32 u64 each.
    u64 EcA[32], EcB[32];
    {
        const int strd = (grp == 0) ? N_ : 1;
        const int offA = (grp == 0) ? j0 : j0 * N_;
        const int offB = (grp == 0) ? j1 : j1 * N_;
#pragma unroll
        for (int i = 0; i < 32; ++i) {
            EcA[i] = pack2(__expf(ck[(2 * i) * strd + offA]),
                           __expf(ck[(2 * i + 1) * strd + offA]));
            EcB[i] = pack2(__expf(ck[(2 * i) * strd + offB]),
                           __expf(ck[(2 * i + 1) * strd + offB]));
        }
    }

    const float* Pb   = pot  + (size_t)b * T_ * N_;
    const int*   tagb = tags + b * T_;

    // ---------------- sequence score (64 threads) ----------------
    float ss = 0.f;
    for (int t = tid; t < len; t += N_) {
        int tg = tagb[t];
        ss += Pb[t * N_ + tg];
        if (t >= 1) ss += ck[tagb[t - 1] * N_ + tg];
    }
    red2[tid] = ss;
    __syncthreads();
#pragma unroll
    for (int off = N_ / 2; off >= 1; off >>= 1) {
        if (tid < off) red2[tid] += red2[tid + off];
        __syncthreads();
    }
    const float seq_score = red2[0];
    __syncthreads();

    const int stepsF = (L + 1) >> 1;   // forward applies t = 1..stepsF
    const int stepsB = L - stepsF;     // backward applies t = L..stepsF+1
    const int niter  = stepsF;

    // ---------------- init ----------------
    float cacc, my0, my1, p_cur0, p_cur1, p_nxt0, p_nxt1;
    int pidx, pinc;
    if (grp == 0) {
        cacc   = Pb[0];
        my0    = __expf(Pb[j0] - cacc);
        my1    = __expf(Pb[j1] - cacc);
        p_cur0 = Pb[1 * N_ + j0];  p_cur1 = Pb[1 * N_ + j1];
        p_nxt0 = Pb[2 * N_ + j0];  p_nxt1 = Pb[2 * N_ + j1];
        pidx   = 3;   pinc = 1;
    } else {
        cacc   = Pb[L * N_];
        my0    = __expf(Pb[L * N_ + j0] - cacc);
        my1    = __expf(Pb[L * N_ + j1] - cacc);
        p_cur0 = Pb[(L - 1) * N_ + j0];  p_cur1 = Pb[(L - 1) * N_ + j1];
        p_nxt0 = Pb[(L - 2) * N_ + j0];  p_nxt1 = Pb[(L - 2) * N_ + j1];
        pidx   = L - 3;   pinc = -1;
    }
    float* b0 = &buf[grp][0][0];
    float* b1 = &buf[grp][1][0];
    b0[j0] = my0;
    b0[j1] = my1;
    __syncwarp();

    // ---------------- main loop: uniform, unrolled x4, renorm every 4 ------
    const int nmain = (niter >= 3) ? ((niter - 2) & ~3) : 0;
    for (int i = 0; i < nmain; i += 4) {
        STEP(b0, b1, true)
        STEP(b1, b0, false)
        STEP(b0, b1, false)
        STEP(b1, b0, false)
    }

    // ---------------- tail (2..5 iters, predicated) ----------------
    int cur = 0;
    for (int i = nmain; i < niter; ++i) {
        float* src = cur ? b1 : b0;
        float* dst = cur ? b0 : b1;
        const bool active      = (grp == 0) || (i < stepsB);
        const bool last_active = (grp == 1) && (i == stepsB - 1);
        const float* prow = Pb + max(min(pidx, L), 0) * N_;
        float p_pref0 = prow[j0];
        float p_pref1 = prow[j1];
        pidx += pinc;
        float mult0 = last_active ? 1.0f : __expf(p_cur0);
        float mult1 = last_active ? 1.0f : __expf(p_cur1);
        if (((i & 3) == 0) && active) {
            float a0 = src[0];
            float r  = __fdividef(1.0f, a0);
            mult0 *= r;  mult1 *= r;
            cacc += __logf(a0);
        }
        float sA, sB;
        DUALDOT(src, sA, sB)
        if (active) { my0 = sA * mult0; my1 = sB * mult1; }
        dst[j0] = my0;
        dst[j1] = my1;
        __syncwarp();
        p_cur0 = p_nxt0;  p_nxt0 = p_pref0;
        p_cur1 = p_nxt1;  p_nxt1 = p_pref1;
        cur ^= 1;
    }

    // ---------------- combine: Z = sum_j alpha_m[j] * w_m[j] ----------------
    // tid spans 0..63 == all states; ONE product per thread (R13's +32 term
    // double-counted and read out of bounds -> NaN).
    if (tid == 32) c_share = cacc;            // backward warp's log-offset
    __syncthreads();
    red2[tid] = buf[0][cur][tid] * buf[1][cur][tid];
    __syncthreads();
#pragma unroll
    for (int off = N_ / 2; off >= 1; off >>= 1) {
        if (tid < off) red2[tid] += red2[tid + off];
        __syncthreads();
    }

    if (tid == 0) {
        float log_norm = cacc + c_share + logf(red2[0]);
        g_loss[b] = -(seq_score - log_norm) * sw[b];
        __threadfence();
        unsigned old = atomicInc(&g_count, B_ - 1);   // wraps -> self-resetting
        is_last = (old == B_ - 1);
    }
    __syncthreads();

    // ---------------- last block reduces all losses ----------------
    if (is_last) {
        volatile float* gl = g_loss;      // bypass L1 (other SMs' writes)
        red2[tid] = gl[tid] + gl[tid + N_];
        __syncthreads();
#pragma unroll
        for (int off = N_ / 2; off >= 1; off >>= 1) {
            if (tid < off) red2[tid] += red2[tid + off];
            __syncthreads();
        }
        if (tid == 0) out[0] = red2[0] * (1.0f / (float)B_);
    }
}

extern "C" void kernel_launch(void* const* d_in, const int* in_sizes, int n_in,
                              void* d_out, int out_size)
{
    const float* pot    = (const float*)d_in[0];
    const int*   tags   = (const int*)  d_in[1];
    const int*   seqlen = (const int*)  d_in[2];
    const float* ck     = (const float*)d_in[3];
    const float* sw     = (const float*)d_in[4];

    crf_forward_kernel<<<B_, N_>>>(pot, tags, seqlen, ck, sw, (float*)d_out);
}

// round 15
// speedup vs baseline: 1.0818x; 1.0269x over previous
#include <cuda_runtime.h>

#define B_ 128
#define T_ 1024
#define N_ 64

// Per-batch losses + completion counter; reduced by the last-arriving block.
__device__ float g_loss[B_];
__device__ unsigned g_count = 0;   // wraps to 0 every launch via atomicInc(.,B_-1)

typedef unsigned long long u64;

__device__ __forceinline__ u64 pack2(float lo, float hi) {
    u64 d;
    asm("mov.b64 %0, {%1, %2};" : "=l"(d)
        : "r"(__float_as_uint(lo)), "r"(__float_as_uint(hi)));
    return d;
}
__device__ __forceinline__ float unpack_sum(u64 v) {
    unsigned a, b;
    asm("mov.b64 {%0, %1}, %2;" : "=r"(a), "=r"(b) : "l"(v));
    return __uint_as_float(a) + __uint_as_float(b);
}
__device__ __forceinline__ u64 ffma2(u64 a, u64 b, u64 c) {
    u64 d;
    asm("fma.rn.f32x2 %0, %1, %2, %3;" : "=l"(d) : "l"(a), "l"(b), "l"(c));
    return d;
}
__device__ __forceinline__ u64 fadd2(u64 a, u64 b) {
    u64 d;
    asm("add.rn.f32x2 %0, %1, %2;" : "=l"(d) : "l"(a), "l"(b));
    return d;
}

// Dual dot products (states A=2*lane, B=2*lane+1) sharing one pass of
// 16x LDS.128 over the alpha vector: 64x FFMA2, 4 accumulators per state.
#define DUALDOT(SRC, SA, SB)                                               \
    {                                                                      \
        const ulonglong2* a4_ = (const ulonglong2*)(SRC);                  \
        u64 A0 = 0ull, A1 = 0ull, A2 = 0ull, A3 = 0ull;                    \
        u64 B0 = 0ull, B1 = 0ull, B2 = 0ull, B3 = 0ull;                    \
        _Pragma("unroll")                                                  \
        for (int k = 0; k < 16; ++k) {                                     \
            ulonglong2 v = a4_[k];                                         \
            if (k & 1) {                                                   \
                A2 = ffma2(v.x, EcA[2 * k],     A2);                       \
                A3 = ffma2(v.y, EcA[2 * k + 1], A3);                       \
                B2 = ffma2(v.x, EcB[2 * k],     B2);                       \
                B3 = ffma2(v.y, EcB[2 * k + 1], B3);                       \
            } else {                                                       \
                A0 = ffma2(v.x, EcA[2 * k],     A0);                       \
                A1 = ffma2(v.y, EcA[2 * k + 1], A1);                       \
                B0 = ffma2(v.x, EcB[2 * k],     B0);                       \
                B1 = ffma2(v.y, EcB[2 * k + 1], B1);                       \
            }                                                              \
        }                                                                  \
        A0 = fadd2(A0, A1); A2 = fadd2(A2, A3); A0 = fadd2(A0, A2);        \
        B0 = fadd2(B0, B1); B2 = fadd2(B2, B3); B0 = fadd2(B0, B2);        \
        (SA) = unpack_sum(A0);                                             \
        (SB) = unpack_sum(B0);                                             \
    }

// One scan step. The exp-multiplier (e0,e1) was computed LAST step, so the
// first work after the previous syncwarp is the dot's LDS stream. Next step's
// exp + prefetch issue before this step's syncwarp (independent of new alpha).
#define STEP(SRC, DST, RENORM)                                             \
    {                                                                      \
        float mult0 = e0, mult1 = e1;                                      \
        if (RENORM) {                                                      \
            float a0 = (SRC)[0];                                           \
            float r  = __fdividef(1.0f, a0);                               \
            mult0 *= r;  mult1 *= r;                                       \
            cacc += __logf(a0);                                            \
        }                                                                  \
        float sA, sB;                                                      \
        DUALDOT(SRC, sA, sB)                                               \
        my0 = sA * mult0;                                                  \
        my1 = sB * mult1;                                                  \
        *(float2*)((DST) + jj) = make_float2(my0, my1);                    \
        float2 p_pref = *(const float2*)(Pb + max(pidx, 0) * N_ + jj);     \
        pidx += pinc;                                                      \
        e0 = __expf(p_cur.x);                                              \
        e1 = __expf(p_cur.y);                                              \
        p_cur = p_nxt;  p_nxt = p_pref;                                    \
        __syncwarp();                                                      \
    }

// 64 threads (2 warps): warp 0 = FORWARD half-chain, warp 1 = BACKWARD
// half-chain; lane owns states {2*lane, 2*lane+1}. Intra-warp sync only.
// Meet at m = ceil(L/2): Z = sum_j alpha_m[j] * w_m[j]. Last-arriving block
// reduces g_loss into out.
__global__ void __launch_bounds__(N_, 1) crf_forward_kernel(
    const float* __restrict__ pot,     // (B,T,N)
    const int*   __restrict__ tags,    // (B,T)
    const int*   __restrict__ seqlen,  // (B,)
    const float* __restrict__ ck,      // (N,N)
    const float* __restrict__ sw,      // (B,)
    float*       __restrict__ out)     // (1,)
{
    const int tid  = threadIdx.x;
    const int b    = blockIdx.x;
    const int grp  = tid >> 5;         // 0 = forward, 1 = backward
    const int lane = tid & 31;
    const int jj   = 2 * lane;         // first owned state (pair jj, jj+1)
    const int len  = seqlen[b];
    const int L    = len - 1;          // len >= T/2 = 512

    __shared__ __align__(16) float buf[2][2][N_];  // [grp][parity][state]
    __shared__ float red2[2 * N_];
    __shared__ float c_share;
    __shared__ int   is_last;

    // E registers: columns (fwd) / rows (bwd) jj and jj+1 of exp(ck).
    u64 EcA[32], EcB[32];
    {
        const int strd = (grp == 0) ? N_ : 1;
        const int offA = (grp == 0) ? jj : jj * N_;
        const int offB = (grp == 0) ? (jj + 1) : (jj + 1) * N_;
#pragma unroll
        for (int i = 0; i < 32; ++i) {
            EcA[i] = pack2(__expf(ck[(2 * i) * strd + offA]),
                           __expf(ck[(2 * i + 1) * strd + offA]));
            EcB[i] = pack2(__expf(ck[(2 * i) * strd + offB]),
                           __expf(ck[(2 * i + 1) * strd + offB]));
        }
    }

    const float* Pb   = pot  + (size_t)b * T_ * N_;
    const int*   tagb = tags + b * T_;

    // ---------------- sequence score (64 threads) ----------------
    float ss = 0.f;
    for (int t = tid; t < len; t += N_) {
        int tg = tagb[t];
        ss += Pb[t * N_ + tg];
        if (t >= 1) ss += ck[tagb[t - 1] * N_ + tg];
    }
    red2[tid] = ss;
    __syncthreads();
#pragma unroll
    for (int off = N_ / 2; off >= 1; off >>= 1) {
        if (tid < off) red2[tid] += red2[tid + off];
        __syncthreads();
    }
    const float seq_score = red2[0];
    __syncthreads();

    const int stepsF = (L + 1) >> 1;   // forward applies t = 1..stepsF
    const int stepsB = L - stepsF;     // backward applies t = L..stepsF+1
    const int niter  = stepsF;

    // ---------------- init (pipelined-e convention) ----------------
    // Entering the loop: e0,e1 = exp(pot of the step applied NOW);
    // p_cur = pot of next step; p_nxt = one further; prefetch 3 ahead.
    float cacc, my0, my1, e0, e1;
    float2 p_cur, p_nxt;
    int pidx, pinc;
    if (grp == 0) {
        cacc  = Pb[0];
        my0   = __expf(Pb[jj]     - cacc);
        my1   = __expf(Pb[jj + 1] - cacc);
        e0    = __expf(Pb[1 * N_ + jj]);
        e1    = __expf(Pb[1 * N_ + jj + 1]);
        p_cur = *(const float2*)(Pb + 2 * N_ + jj);
        p_nxt = *(const float2*)(Pb + 3 * N_ + jj);
        pidx  = 4;   pinc = 1;
    } else {
        cacc  = Pb[L * N_];
        my0   = __expf(Pb[L * N_ + jj]     - cacc);
        my1   = __expf(Pb[L * N_ + jj + 1] - cacc);
        e0    = __expf(Pb[(L - 1) * N_ + jj]);
        e1    = __expf(Pb[(L - 1) * N_ + jj + 1]);
        p_cur = *(const float2*)(Pb + (L - 2) * N_ + jj);
        p_nxt = *(const float2*)(Pb + (L - 3) * N_ + jj);
        pidx  = L - 4;   pinc = -1;
    }
    float* b0 = &buf[grp][0][0];
    float* b1 = &buf[grp][1][0];
    *(float2*)(b0 + jj) = make_float2(my0, my1);
    __syncwarp();

    // ---------------- main loop: uniform, unrolled x4, renorm every 4 ------
    const int nmain = (niter >= 3) ? ((niter - 2) & ~3) : 0;
    for (int i = 0; i < nmain; i += 4) {
        STEP(b0, b1, true)
        STEP(b1, b0, false)
        STEP(b0, b1, false)
        STEP(b1, b0, false)
    }

    // ---------------- tail (2..5 iters, predicated, pipelined-e) -----------
    int cur = 0;
    for (int i = nmain; i < niter; ++i) {
        float* src = cur ? b1 : b0;
        float* dst = cur ? b0 : b1;
        const bool active      = (grp == 0) || (i < stepsB);
        const bool last_active = (grp == 1) && (i == stepsB - 1);
        float mult0 = last_active ? 1.0f : e0;
        float mult1 = last_active ? 1.0f : e1;
        if (((i & 3) == 0) && active) {
            float a0 = src[0];
            float r  = __fdividef(1.0f, a0);
            mult0 *= r;  mult1 *= r;
            cacc += __logf(a0);
        }
        float sA, sB;
        DUALDOT(src, sA, sB)
        if (active) { my0 = sA * mult0; my1 = sB * mult1; }
        *(float2*)(dst + jj) = make_float2(my0, my1);
        float2 p_pref = *(const float2*)(Pb + max(min(pidx, L), 0) * N_ + jj);
        pidx += pinc;
        e0 = __expf(p_cur.x);
        e1 = __expf(p_cur.y);
        p_cur = p_nxt;  p_nxt = p_pref;
        __syncwarp();
        cur ^= 1;
    }

    // ---------------- combine: Z = sum_j alpha_m[j] * w_m[j] ----------------
    if (tid == 32) c_share = cacc;            // backward warp's log-offset
    __syncthreads();
    red2[tid] = buf[0][cur][tid] * buf[1][cur][tid];
    __syncthreads();
#pragma unroll
    for (int off = N_ / 2; off >= 1; off >>= 1) {
        if (tid < off) red2[tid] += red2[tid + off];
        __syncthreads();
    }

    if (tid == 0) {
        float log_norm = cacc + c_share + logf(red2[0]);
        g_loss[b] = -(seq_score - log_norm) * sw[b];
        __threadfence();
        unsigned old = atomicInc(&g_count, B_ - 1);   // wraps -> self-resetting
        is_last = (old == B_ - 1);
    }
    __syncthreads();

    // ---------------- last block reduces all losses ----------------
    if (is_last) {
        volatile float* gl = g_loss;      // bypass L1 (other SMs' writes)
        red2[tid] = gl[tid] + gl[tid + N_];
        __syncthreads();
#pragma unroll
        for (int off = N_ / 2; off >= 1; off >>= 1) {
            if (tid < off) red2[tid] += red2[tid + off];
            __syncthreads();
        }
        if (tid == 0) out[0] = red2[0] * (1.0f / (float)B_);
    }
}

extern "C" void kernel_launch(void* const* d_in, const int* in_sizes, int n_in,
                              void* d_out, int out_size)
{
    const float* pot    = (const float*)d_in[0];
    const int*   tags   = (const int*)  d_in[1];
    const int*   seqlen = (const int*)  d_in[2];
    const float* ck     = (const float*)d_in[3];
    const float* sw     = (const float*)d_in[4];

    crf_forward_kernel<<<B_, N_>>>(pot, tags, seqlen, ck, sw, (float*)d_out);
}